// round 11
// baseline (speedup 1.0000x reference)
#include <cuda_runtime.h>
#include <math.h>

#define N_NODES 50000
#define N_EDGES 800000
#define FIN 128
#define FOUT 64
#define CAP 96   // max in-degree bucket capacity (Poisson(16): P(>=96) ~ 1e-40)

// ---------------- device scratch (no allocations allowed) ----------------
__device__ int   d_cnt[N_NODES];
__device__ float d_dinv[N_NODES];
__device__ int   d_csr[(size_t)N_NODES * CAP];   // padded buckets
__device__ float d_g1[(size_t)N_NODES * FOUT];   // dinv-scaled layer-1 features
__device__ float d_g2[N_NODES];                  // dinv-scaled layer-2 scalar
__device__ float d_w[FOUT];                      // W2 @ Wfc  (collapsed)
__device__ float d_c;                            // b2 @ Wfc + bfc

// ---------------- K0: zero counts + collapse W2@Wfc ----------------
__global__ void init_kernel(const float* __restrict__ W2,
                            const float* __restrict__ b2,
                            const float* __restrict__ Wfc,
                            const float* __restrict__ bfc) {
    int i = blockIdx.x * blockDim.x + threadIdx.x;
    if (i < N_NODES) d_cnt[i] = 0;
    if (i < FOUT) {
        float s = 0.f;
        #pragma unroll 8
        for (int j = 0; j < FOUT; j++) s = fmaf(W2[i * FOUT + j], Wfc[j], s);
        d_w[i] = s;
    }
    if (i == FOUT) {
        float s = 0.f;
        for (int j = 0; j < FOUT; j++) s = fmaf(b2[j], Wfc[j], s);
        d_c = s + bfc[0];
    }
}

// ---------------- K1: bucket fill (4 edges/thread, independent atomics) ----------------
__global__ void __launch_bounds__(512) fill_kernel(const int4* __restrict__ src4,
                                                   const int4* __restrict__ dst4) {
    int t = blockIdx.x * blockDim.x + threadIdx.x;
    if (t >= N_EDGES / 4) return;
    int4 s = src4[t];
    int4 d = dst4[t];
    int p0 = atomicAdd(&d_cnt[d.x], 1);
    int p1 = atomicAdd(&d_cnt[d.y], 1);
    int p2 = atomicAdd(&d_cnt[d.z], 1);
    int p3 = atomicAdd(&d_cnt[d.w], 1);
    if (p0 < CAP) d_csr[(size_t)d.x * CAP + p0] = s.x;
    if (p1 < CAP) d_csr[(size_t)d.y * CAP + p1] = s.y;
    if (p2 < CAP) d_csr[(size_t)d.z * CAP + p2] = s.z;
    if (p3 < CAP) d_csr[(size_t)d.w * CAP + p3] = s.w;
}

// ---------------- K2: dinv = rsqrt(deg + 1) ----------------
__global__ void dinv_kernel() {
    int i = blockIdx.x * blockDim.x + threadIdx.x;
    if (i < N_NODES) d_dinv[i] = rsqrtf((float)(d_cnt[i] + 1));
}

// ---------------- K3: g1 = dinv * (x @ W1)  (thread-per-row, 64 reg accumulators) ----------------
__global__ void __launch_bounds__(128) gemm1_kernel(const float* __restrict__ x,
                                                    const float* __restrict__ W1) {
    __shared__ float Ws[FIN * FOUT];   // 32 KB
    int tid = threadIdx.x;
    for (int i = tid * 4; i < FIN * FOUT; i += blockDim.x * 4)
        *(float4*)&Ws[i] = *(const float4*)&W1[i];
    __syncthreads();

    int row = blockIdx.x * blockDim.x + tid;
    if (row >= N_NODES) return;

    float acc[FOUT];
    #pragma unroll
    for (int f = 0; f < FOUT; f++) acc[f] = 0.f;

    const float4* xr = (const float4*)(x + (size_t)row * FIN);
    #pragma unroll 1
    for (int k4 = 0; k4 < FIN / 4; k4++) {
        float4 xv = xr[k4];
        float xk[4] = {xv.x, xv.y, xv.z, xv.w};
        #pragma unroll
        for (int kk = 0; kk < 4; kk++) {
            const float4* wr = (const float4*)&Ws[(k4 * 4 + kk) * FOUT];
            #pragma unroll
            for (int f4 = 0; f4 < FOUT / 4; f4++) {
                float4 wv = wr[f4];
                acc[f4 * 4 + 0] = fmaf(xk[kk], wv.x, acc[f4 * 4 + 0]);
                acc[f4 * 4 + 1] = fmaf(xk[kk], wv.y, acc[f4 * 4 + 1]);
                acc[f4 * 4 + 2] = fmaf(xk[kk], wv.z, acc[f4 * 4 + 2]);
                acc[f4 * 4 + 3] = fmaf(xk[kk], wv.w, acc[f4 * 4 + 3]);
            }
        }
    }
    float dv = d_dinv[row];
    float* go = d_g1 + (size_t)row * FOUT;
    #pragma unroll
    for (int f4 = 0; f4 < FOUT / 4; f4++) {
        float4 v = make_float4(acc[f4 * 4 + 0] * dv, acc[f4 * 4 + 1] * dv,
                               acc[f4 * 4 + 2] * dv, acc[f4 * 4 + 3] * dv);
        *(float4*)&go[f4 * 4] = v;
    }
}

// ---------------- K4: layer-1 aggregate + bias + relu + collapsed dot -> g2 ----------------
// warp per node; lane holds feats (2*lane, 2*lane+1)
__global__ void agg1_kernel(const float* __restrict__ b1) {
    int warp = (blockIdx.x * blockDim.x + threadIdx.x) >> 5;
    int lane = threadIdx.x & 31;
    if (warp >= N_NODES) return;
    int d = warp;
    int n = d_cnt[d];
    if (n > CAP) n = CAP;
    const int* bucket = d_csr + (size_t)d * CAP;
    const float2* g = (const float2*)d_g1;
    float2 self = g[d * 32 + lane];
    float a0 = self.x, a1 = self.y;
    int e = 0;
    for (; e + 1 < n; e += 2) {
        int s0 = bucket[e], s1 = bucket[e + 1];
        float2 v0 = g[s0 * 32 + lane];
        float2 v1 = g[s1 * 32 + lane];
        a0 += v0.x + v1.x;
        a1 += v0.y + v1.y;
    }
    if (e < n) {
        int s = bucket[e];
        float2 v = g[s * 32 + lane];
        a0 += v.x; a1 += v.y;
    }
    float dv = d_dinv[d];
    float r0 = fmaxf(fmaf(dv, a0, b1[2 * lane]),     0.f);
    float r1 = fmaxf(fmaf(dv, a1, b1[2 * lane + 1]), 0.f);
    float p = fmaf(r0, d_w[2 * lane], r1 * d_w[2 * lane + 1]);
    #pragma unroll
    for (int o = 16; o > 0; o >>= 1) p += __shfl_xor_sync(0xffffffffu, p, o);
    if (lane == 0) d_g2[d] = dv * p;
}

// ---------------- K5: layer-2 scalar aggregate + sigmoid ----------------
__global__ void agg2_kernel(float* __restrict__ out) {
    int warp = (blockIdx.x * blockDim.x + threadIdx.x) >> 5;
    int lane = threadIdx.x & 31;
    if (warp >= N_NODES) return;
    int d = warp;
    int n = d_cnt[d];
    if (n > CAP) n = CAP;
    const int* bucket = d_csr + (size_t)d * CAP;
    float acc = 0.f;
    for (int e = lane; e < n; e += 32) acc += d_g2[bucket[e]];
    #pragma unroll
    for (int o = 16; o > 0; o >>= 1) acc += __shfl_xor_sync(0xffffffffu, acc, o);
    if (lane == 0) {
        float z = fmaf(d_dinv[d], acc + d_g2[d], d_c);
        out[d] = 1.f / (1.f + expf(-z));
    }
}

// ---------------- launch ----------------
extern "C" void kernel_launch(void* const* d_in, const int* in_sizes, int n_in,
                              void* d_out, int out_size) {
    const float* x   = (const float*)d_in[0];
    const int*   ei  = (const int*)d_in[1];
    const float* W1  = (const float*)d_in[2];
    const float* b1  = (const float*)d_in[3];
    const float* W2  = (const float*)d_in[4];
    const float* b2  = (const float*)d_in[5];
    const float* Wfc = (const float*)d_in[6];
    const float* bfc = (const float*)d_in[7];
    float* out = (float*)d_out;

    const int4* src4 = (const int4*)ei;               // edge_index[0]
    const int4* dst4 = (const int4*)(ei + N_EDGES);   // edge_index[1]

    init_kernel <<<(N_NODES + 255) / 256, 256>>>(W2, b2, Wfc, bfc);
    fill_kernel <<<(N_EDGES / 4 + 511) / 512, 512>>>(src4, dst4);
    dinv_kernel <<<(N_NODES + 255) / 256, 256>>>();
    gemm1_kernel<<<(N_NODES + 127) / 128, 128>>>(x, W1);
    agg1_kernel <<<(N_NODES * 32 + 255) / 256, 256>>>(b1);
    agg2_kernel <<<(N_NODES * 32 + 255) / 256, 256>>>(out);
}

// round 12
// speedup vs baseline: 1.0007x; 1.0007x over previous
#include <cuda_runtime.h>
#include <math.h>

#define N_NODES 50000
#define N_EDGES 800000
#define FIN 128
#define FOUT 64
#define CAP 96   // max in-degree bucket capacity (Poisson(16): P(>=96) ~ 1e-40)

// ---------------- device scratch (no allocations allowed) ----------------
__device__ int   d_cnt[N_NODES];
__device__ float d_dinv[N_NODES];
__device__ int   d_csr[(size_t)N_NODES * CAP];   // padded buckets
__device__ float d_g1[(size_t)N_NODES * FOUT];   // dinv-scaled layer-1 features
__device__ float d_g2[N_NODES];                  // dinv-scaled layer-2 scalar
__device__ float d_w[FOUT];                      // W2 @ Wfc  (collapsed)
__device__ float d_c;                            // b2 @ Wfc + bfc

// ---------------- K0: zero counts + collapse W2@Wfc ----------------
__global__ void init_kernel(const float* __restrict__ W2,
                            const float* __restrict__ b2,
                            const float* __restrict__ Wfc,
                            const float* __restrict__ bfc) {
    int i = blockIdx.x * blockDim.x + threadIdx.x;
    if (i < N_NODES) d_cnt[i] = 0;
    if (i < FOUT) {
        float s = 0.f;
        #pragma unroll 8
        for (int j = 0; j < FOUT; j++) s = fmaf(W2[i * FOUT + j], Wfc[j], s);
        d_w[i] = s;
    }
    if (i == FOUT) {
        float s = 0.f;
        for (int j = 0; j < FOUT; j++) s = fmaf(b2[j], Wfc[j], s);
        d_c = s + bfc[0];
    }
}

// ---------------- K1: bucket fill (4 edges/thread, independent atomics) ----------------
__global__ void __launch_bounds__(512) fill_kernel(const int4* __restrict__ src4,
                                                   const int4* __restrict__ dst4) {
    int t = blockIdx.x * blockDim.x + threadIdx.x;
    if (t >= N_EDGES / 4) return;
    int4 s = src4[t];
    int4 d = dst4[t];
    int p0 = atomicAdd(&d_cnt[d.x], 1);
    int p1 = atomicAdd(&d_cnt[d.y], 1);
    int p2 = atomicAdd(&d_cnt[d.z], 1);
    int p3 = atomicAdd(&d_cnt[d.w], 1);
    if (p0 < CAP) d_csr[(size_t)d.x * CAP + p0] = s.x;
    if (p1 < CAP) d_csr[(size_t)d.y * CAP + p1] = s.y;
    if (p2 < CAP) d_csr[(size_t)d.z * CAP + p2] = s.z;
    if (p3 < CAP) d_csr[(size_t)d.w * CAP + p3] = s.w;
}

// ---------------- K2: dinv = rsqrt(deg + 1) ----------------
__global__ void dinv_kernel() {
    int i = blockIdx.x * blockDim.x + threadIdx.x;
    if (i < N_NODES) d_dinv[i] = rsqrtf((float)(d_cnt[i] + 1));
}

// ---------------- K3: g1 = dinv * (x @ W1)  (thread-per-row, 64 reg accumulators) ----------------
__global__ void __launch_bounds__(128) gemm1_kernel(const float* __restrict__ x,
                                                    const float* __restrict__ W1) {
    __shared__ float Ws[FIN * FOUT];   // 32 KB
    int tid = threadIdx.x;
    for (int i = tid * 4; i < FIN * FOUT; i += blockDim.x * 4)
        *(float4*)&Ws[i] = *(const float4*)&W1[i];
    __syncthreads();

    int row = blockIdx.x * blockDim.x + tid;
    if (row >= N_NODES) return;

    float acc[FOUT];
    #pragma unroll
    for (int f = 0; f < FOUT; f++) acc[f] = 0.f;

    const float4* xr = (const float4*)(x + (size_t)row * FIN);
    #pragma unroll 1
    for (int k4 = 0; k4 < FIN / 4; k4++) {
        float4 xv = xr[k4];
        float xk[4] = {xv.x, xv.y, xv.z, xv.w};
        #pragma unroll
        for (int kk = 0; kk < 4; kk++) {
            const float4* wr = (const float4*)&Ws[(k4 * 4 + kk) * FOUT];
            #pragma unroll
            for (int f4 = 0; f4 < FOUT / 4; f4++) {
                float4 wv = wr[f4];
                acc[f4 * 4 + 0] = fmaf(xk[kk], wv.x, acc[f4 * 4 + 0]);
                acc[f4 * 4 + 1] = fmaf(xk[kk], wv.y, acc[f4 * 4 + 1]);
                acc[f4 * 4 + 2] = fmaf(xk[kk], wv.z, acc[f4 * 4 + 2]);
                acc[f4 * 4 + 3] = fmaf(xk[kk], wv.w, acc[f4 * 4 + 3]);
            }
        }
    }
    float dv = d_dinv[row];
    float* go = d_g1 + (size_t)row * FOUT;
    #pragma unroll
    for (int f4 = 0; f4 < FOUT / 4; f4++) {
        float4 v = make_float4(acc[f4 * 4 + 0] * dv, acc[f4 * 4 + 1] * dv,
                               acc[f4 * 4 + 2] * dv, acc[f4 * 4 + 3] * dv);
        *(float4*)&go[f4 * 4] = v;
    }
}

// ---------------- K4: layer-1 aggregate + bias + relu + collapsed dot -> g2 ----------------
// warp per node; lane holds feats (2*lane, 2*lane+1)
__global__ void agg1_kernel(const float* __restrict__ b1) {
    int warp = (blockIdx.x * blockDim.x + threadIdx.x) >> 5;
    int lane = threadIdx.x & 31;
    if (warp >= N_NODES) return;
    int d = warp;
    int n = d_cnt[d];
    if (n > CAP) n = CAP;
    const int* bucket = d_csr + (size_t)d * CAP;
    const float2* g = (const float2*)d_g1;
    float2 self = g[d * 32 + lane];
    float a0 = self.x, a1 = self.y;
    int e = 0;
    for (; e + 1 < n; e += 2) {
        int s0 = bucket[e], s1 = bucket[e + 1];
        float2 v0 = g[s0 * 32 + lane];
        float2 v1 = g[s1 * 32 + lane];
        a0 += v0.x + v1.x;
        a1 += v0.y + v1.y;
    }
    if (e < n) {
        int s = bucket[e];
        float2 v = g[s * 32 + lane];
        a0 += v.x; a1 += v.y;
    }
    float dv = d_dinv[d];
    float r0 = fmaxf(fmaf(dv, a0, b1[2 * lane]),     0.f);
    float r1 = fmaxf(fmaf(dv, a1, b1[2 * lane + 1]), 0.f);
    float p = fmaf(r0, d_w[2 * lane], r1 * d_w[2 * lane + 1]);
    #pragma unroll
    for (int o = 16; o > 0; o >>= 1) p += __shfl_xor_sync(0xffffffffu, p, o);
    if (lane == 0) d_g2[d] = dv * p;
}

// ---------------- K5: layer-2 scalar aggregate + sigmoid ----------------
__global__ void agg2_kernel(float* __restrict__ out) {
    int warp = (blockIdx.x * blockDim.x + threadIdx.x) >> 5;
    int lane = threadIdx.x & 31;
    if (warp >= N_NODES) return;
    int d = warp;
    int n = d_cnt[d];
    if (n > CAP) n = CAP;
    const int* bucket = d_csr + (size_t)d * CAP;
    float acc = 0.f;
    for (int e = lane; e < n; e += 32) acc += d_g2[bucket[e]];
    #pragma unroll
    for (int o = 16; o > 0; o >>= 1) acc += __shfl_xor_sync(0xffffffffu, acc, o);
    if (lane == 0) {
        float z = fmaf(d_dinv[d], acc + d_g2[d], d_c);
        out[d] = 1.f / (1.f + expf(-z));
    }
}

// ---------------- launch ----------------
extern "C" void kernel_launch(void* const* d_in, const int* in_sizes, int n_in,
                              void* d_out, int out_size) {
    const float* x   = (const float*)d_in[0];
    const int*   ei  = (const int*)d_in[1];
    const float* W1  = (const float*)d_in[2];
    const float* b1  = (const float*)d_in[3];
    const float* W2  = (const float*)d_in[4];
    const float* b2  = (const float*)d_in[5];
    const float* Wfc = (const float*)d_in[6];
    const float* bfc = (const float*)d_in[7];
    float* out = (float*)d_out;

    const int4* src4 = (const int4*)ei;               // edge_index[0]
    const int4* dst4 = (const int4*)(ei + N_EDGES);   // edge_index[1]

    init_kernel <<<(N_NODES + 255) / 256, 256>>>(W2, b2, Wfc, bfc);
    fill_kernel <<<(N_EDGES / 4 + 511) / 512, 512>>>(src4, dst4);
    dinv_kernel <<<(N_NODES + 255) / 256, 256>>>();
    gemm1_kernel<<<(N_NODES + 127) / 128, 128>>>(x, W1);
    agg1_kernel <<<(N_NODES * 32 + 255) / 256, 256>>>(b1);
    agg2_kernel <<<(N_NODES * 32 + 255) / 256, 256>>>(out);
}